// round 14
// baseline (speedup 1.0000x reference)
#include <cuda_runtime.h>
#include <cuda_bf16.h>
#include <cuda_fp16.h>
#include <cstdint>

// ---------------------------------------------------------------------------
// SpookyNetAttention — split-bf16 (hi/lo, 3-product) GEMM on mma.sync,
// ldmatrix fragments, persistent CTAs + prefetch, fragment-order fp16 scratch.
// R13: 64x64 warp tiles, 8 warps/CTA (256 thr) -> smem bytes/MMA 128->85,
// flipping the binding resource from L1/crossbar to the tensor pipe.
// ---------------------------------------------------------------------------

#define KD   128
#define MD   256
#define TM   128
#define NTH  256            // 8 warps, 2x4 warp grid, warp tile 64x64
#define N_MAX 262144
#define MAX_NB (N_MAX / TM)
#define SP   136            // padded bf16 row stride; word stride 68 = 4 mod 32
#define PGRID 152           // persistent CTAs (GB300: 152 SMs)

// smem byte offsets
#define SO_BH   0                       // [256][136] bf16
#define SO_BL   69632
#define SO_AH   139264                  // [128][136] bf16
#define SO_AL   174080
#define SO_H    208896                  // 128 floats
#define SO_S    209408                  // 256 floats
#define SO_RED  210432                  // 3 x 2KB reduction buffers
#define SO_SC   216576                  // 128 floats
#define SO_RR   217088                  // 8 floats (warp maxes)
#define SO_CT   217152                  // next-tile broadcast (int)
#define SMEM_BYTES 217216

#define DAL (SO_AL - SO_AH)
#define DBL (SO_BL - SO_BH)

// device scratch (allocation-free per harness rules)
__device__ __nv_bfloat16 g_BT_hi[MD * KD];
__device__ __nv_bfloat16 g_BT_lo[MD * KD];
__device__ uint4    g_UK4[(size_t)N_MAX * MD / 8];  // exp(Uk-h-bmax), half,
                                                    // fragment order
__device__ float    g_Spart[MAX_NB * MD];
__device__ float    g_bmax[MAX_NB];
__device__ float    g_S[MD];
__device__ unsigned g_gmax_enc;
__device__ float    g_gmax;
__device__ int      g_ctrK, g_ctrQ;

// ---------------- helpers ----------------
__device__ __forceinline__ unsigned enc_f(float f) {
    unsigned u = __float_as_uint(f);
    return (u & 0x80000000u) ? ~u : (u | 0x80000000u);
}
__device__ __forceinline__ float dec_f(unsigned u) {
    u = (u & 0x80000000u) ? (u & 0x7FFFFFFFu) : ~u;
    return __uint_as_float(u);
}
__device__ __forceinline__ uint32_t smem_u32(const void* p) {
    uint32_t a;
    asm("{ .reg .u64 t; cvta.to.shared.u64 t, %1; cvt.u32.u64 %0, t; }" : "=r"(a) : "l"(p));
    return a;
}
__device__ __forceinline__ void mma16816(float c[4], const uint32_t a[4],
                                         uint32_t b0, uint32_t b1) {
    asm volatile(
        "mma.sync.aligned.m16n8k16.row.col.f32.bf16.bf16.f32 "
        "{%0,%1,%2,%3}, {%4,%5,%6,%7}, {%8,%9}, {%0,%1,%2,%3};"
        : "+f"(c[0]), "+f"(c[1]), "+f"(c[2]), "+f"(c[3])
        : "r"(a[0]), "r"(a[1]), "r"(a[2]), "r"(a[3]), "r"(b0), "r"(b1));
}
#define LDSM4(R, A)                                                         \
    asm volatile("ldmatrix.sync.aligned.m8n8.x4.shared.b16 {%0,%1,%2,%3}, [%4];" \
        : "=r"((R)[0]), "=r"((R)[1]), "=r"((R)[2]), "=r"((R)[3]) : "r"(A))

__device__ __forceinline__ uint32_t pack_h2(float a, float b) {
    __half2 h = __floats2half2_rn(a, b);
    return *(uint32_t*)&h;
}

// ---------------- shared device functions ----------------

// B (omega^T hi/lo) -> padded smem. 256 threads, once per CTA.
__device__ __forceinline__ void load_B(char* sm, int tid) {
    #pragma unroll
    for (int it = 0; it < 32; ++it) {
        int c = tid + it * NTH;
        int row = c >> 5;
        int pos = (c & 31) * 4;
        uint2 vh = *(const uint2*)((const char*)g_BT_hi + (row * KD + pos) * 2);
        uint2 vl = *(const uint2*)((const char*)g_BT_lo + (row * KD + pos) * 2);
        *(uint2*)(sm + SO_BH + (row * SP + pos) * 2) = vh;
        *(uint2*)(sm + SO_BL + (row * SP + pos) * 2) = vl;
    }
}

// A tile: 128 rows fp32 -> bf16 hi/lo padded smem + per-row h.
__device__ __forceinline__ void load_A(const float* __restrict__ X, int base,
                                       char* sm, float* s_h, int tid) {
    const int lane = tid & 31;
    #pragma unroll
    for (int it = 0; it < 16; ++it) {
        int c = tid + it * NTH;
        int row = c >> 5;               // one full row per (warp, it)
        int pos = (c & 31) * 4;
        float4 x = *(const float4*)(X + (size_t)(base + row) * KD + pos);
        float ss = x.x * x.x + x.y * x.y + x.z * x.z + x.w * x.w;
        #pragma unroll
        for (int o = 16; o; o >>= 1) ss += __shfl_xor_sync(0xffffffffu, ss, o);
        if (lane == 0) s_h[row] = ss * 0.04419417382415922f;  // 1/(2*sqrt(128))

        __nv_bfloat16 h0 = __float2bfloat16(x.x), h1 = __float2bfloat16(x.y);
        __nv_bfloat16 h2 = __float2bfloat16(x.z), h3 = __float2bfloat16(x.w);
        __nv_bfloat16 l0 = __float2bfloat16(x.x - __bfloat162float(h0));
        __nv_bfloat16 l1 = __float2bfloat16(x.y - __bfloat162float(h1));
        __nv_bfloat16 l2 = __float2bfloat16(x.z - __bfloat162float(h2));
        __nv_bfloat16 l3 = __float2bfloat16(x.w - __bfloat162float(h3));
        __nv_bfloat162* ph = (__nv_bfloat162*)(sm + SO_AH + (row * SP + pos) * 2);
        __nv_bfloat162* pl = (__nv_bfloat162*)(sm + SO_AL + (row * SP + pos) * 2);
        ph[0] = __nv_bfloat162(h0, h1); ph[1] = __nv_bfloat162(h2, h3);
        pl[0] = __nv_bfloat162(l0, l1); pl[1] = __nv_bfloat162(l2, l3);
    }
}

// Warp GEMM via ldmatrix: 64x64 tile at (rb, cb).
// c element (mf,nf,e): row = rb+mf*16+lq+(e&2?8:0), col = cb+nf*8+lr*2+(e&1).
__device__ __forceinline__ void gemm_warp(uint32_t sb, int rb, int cb,
                                          int lane, float c[4][8][4]) {
    #pragma unroll
    for (int mf = 0; mf < 4; ++mf)
        #pragma unroll
        for (int nf = 0; nf < 8; ++nf)
            #pragma unroll
            for (int e = 0; e < 4; ++e) c[mf][nf][e] = 0.f;

    uint32_t a0 = sb + SO_AH +
        (uint32_t)(((rb + (lane & 15)) * SP + ((lane >> 4) & 1) * 8) * 2);
    uint32_t b0 = sb + SO_BH +
        (uint32_t)(((cb + (lane & 7) + ((lane & 16) ? 8 : 0)) * SP +
                    ((lane & 8) ? 8 : 0)) * 2);

    #pragma unroll 1
    for (int ks = 0; ks < 8; ++ks) {
        uint32_t ah[4][4], al[4][4];
        #pragma unroll
        for (int mf = 0; mf < 4; ++mf) {
            uint32_t aa = a0 + (uint32_t)(mf * 16 * SP * 2);
            LDSM4(ah[mf], aa);
            LDSM4(al[mf], aa + DAL);
        }
        #pragma unroll
        for (int p = 0; p < 4; ++p) {
            uint32_t bh[4], bl[4];
            uint32_t ba = b0 + (uint32_t)(p * 16 * SP * 2);
            LDSM4(bh, ba); LDSM4(bl, ba + DBL);
            #pragma unroll
            for (int mf = 0; mf < 4; ++mf) {
                mma16816(c[mf][2 * p], ah[mf], bh[0], bh[1]);
                mma16816(c[mf][2 * p], ah[mf], bl[0], bl[1]);
                mma16816(c[mf][2 * p], al[mf], bh[0], bh[1]);
                mma16816(c[mf][2 * p + 1], ah[mf], bh[2], bh[3]);
                mma16816(c[mf][2 * p + 1], ah[mf], bl[2], bl[3]);
                mma16816(c[mf][2 * p + 1], al[mf], bh[2], bh[3]);
            }
        }
        a0 += 32; b0 += 32;
    }
}

// ---------------- kernels ----------------
extern "C" __global__ void spooky_prep(const float* __restrict__ omega) {
    int n = blockIdx.x, k = threadIdx.x;
    float v = omega[k * MD + n] * 0.29730177875068026f;   // fold d^-1/4 into B
    __nv_bfloat16 hi = __float2bfloat16(v);
    __nv_bfloat16 lo = __float2bfloat16(v - __bfloat162float(hi));
    g_BT_hi[n * KD + k] = hi;
    g_BT_lo[n * KD + k] = lo;
    if (n == 0 && k == 0) { g_gmax_enc = 0u; g_ctrK = 0; g_ctrQ = 0; }
}

extern "C" __global__ void __launch_bounds__(NTH, 1)
spooky_kpass(const float* __restrict__ Kin, int ntot, int nbt) {
    extern __shared__ __align__(16) char sm[];
    const uint32_t sb = smem_u32(sm);
    float* s_h  = (float*)(sm + SO_H);
    float* redC = (float*)(sm + SO_RED);     // [256 cols][2 wr]
    float* redR = (float*)(sm + SO_RR);      // 8 warp maxes
    int*   s_nt = (int*)(sm + SO_CT);
    const int tid = threadIdx.x, wid = tid >> 5, lane = tid & 31;
    const int lq = lane >> 2, lr = lane & 3;
    const int wr = wid & 1, wc = wid >> 1;
    const int rb = wr * 64, cb = wc * 64;

    if (tid == 0) s_nt[0] = atomicAdd(&g_ctrK, 1);
    __syncthreads();
    int rt = s_nt[0];
    if (rt >= nbt) return;

    load_B(sm, tid);
    load_A(Kin, rt * TM, sm, s_h, tid);
    __syncthreads();

    while (true) {
        float c[4][8][4];
        gemm_warp(sb, rb, cb, lane, c);

        float h8[8];
        #pragma unroll
        for (int s = 0; s < 8; ++s)
            h8[s] = s_h[rb + (s >> 1) * 16 + lq + (s & 1) * 8];

        float umax = -3.402823466e38f;
        #pragma unroll
        for (int mf = 0; mf < 4; ++mf)
            #pragma unroll
            for (int nf = 0; nf < 8; ++nf)
                #pragma unroll
                for (int e = 0; e < 4; ++e) umax = fmaxf(umax, c[mf][nf][e]);
        #pragma unroll
        for (int o = 16; o; o >>= 1)
            umax = fmaxf(umax, __shfl_xor_sync(0xffffffffu, umax, o));
        if (lane == 0) redR[wid] = umax;
        if (tid == 0) s_nt[0] = atomicAdd(&g_ctrK, 1);
        __syncthreads();

        float bmax = redR[0];
        #pragma unroll
        for (int w = 1; w < 8; ++w) bmax = fmaxf(bmax, redR[w]);
        const int nrt = s_nt[0];
        if (tid == 0) {
            g_bmax[rt] = bmax;
            atomicMax(&g_gmax_enc, enc_f(bmax));
        }
        if (nrt < nbt) load_A(Kin, nrt * TM, sm, s_h, tid);  // prefetch overlap

        // epilogue: exp(u-h-bmax) -> half scratch in FRAGMENT ORDER
        float cs[16];
        #pragma unroll
        for (int j = 0; j < 16; ++j) cs[j] = 0.f;
        uint32_t pk[64];
        #pragma unroll
        for (int mf = 0; mf < 4; ++mf)
            #pragma unroll
            for (int nf = 0; nf < 8; ++nf) {
                float v0 = __expf(c[mf][nf][0] - h8[mf * 2] - bmax);
                float v1 = __expf(c[mf][nf][1] - h8[mf * 2] - bmax);
                float v2 = __expf(c[mf][nf][2] - h8[mf * 2 + 1] - bmax);
                float v3 = __expf(c[mf][nf][3] - h8[mf * 2 + 1] - bmax);
                cs[nf * 2 + 0] += v0 + v2;
                cs[nf * 2 + 1] += v1 + v3;
                pk[(mf * 8 + nf) * 2 + 0] = pack_h2(v0, v1);
                pk[(mf * 8 + nf) * 2 + 1] = pack_h2(v2, v3);
            }
        {
            uint4* dst = g_UK4 + ((size_t)rt * 8 + wid) * 512 + lane * 16;
            #pragma unroll
            for (int q = 0; q < 16; ++q)
                dst[q] = make_uint4(pk[4 * q], pk[4 * q + 1], pk[4 * q + 2], pk[4 * q + 3]);
        }
        #pragma unroll
        for (int j = 0; j < 16; ++j) {
            float v = cs[j];
            v += __shfl_xor_sync(0xffffffffu, v, 4);
            v += __shfl_xor_sync(0xffffffffu, v, 8);
            v += __shfl_xor_sync(0xffffffffu, v, 16);
            cs[j] = v;
        }
        if (lq == 0) {
            #pragma unroll
            for (int nf = 0; nf < 8; ++nf)
                #pragma unroll
                for (int e1 = 0; e1 < 2; ++e1)
                    redC[(cb + nf * 8 + lr * 2 + e1) * 2 + wr] = cs[nf * 2 + e1];
        }
        __syncthreads();
        g_Spart[rt * MD + tid] = redC[tid * 2] + redC[tid * 2 + 1];
        __syncthreads();
        if (nrt >= nbt) break;
        rt = nrt;
    }
}

extern "C" __global__ void spooky_fin(int nbt, int ntot) {
    __shared__ float red[256];
    const int j = blockIdx.x, tid = threadIdx.x;
    const float g = dec_f(g_gmax_enc);
    float a = 0.f;
    for (int r = tid; r < nbt; r += 256)
        a += g_Spart[r * MD + j] * __expf(g_bmax[r] - g);
    red[tid] = a;
    __syncthreads();
    for (int s = 128; s; s >>= 1) {
        if (tid < s) red[tid] += red[tid + s];
        __syncthreads();
    }
    if (tid == 0) {
        g_S[j] = (red[0] + (float)ntot * 1e-4f) * 0.0625f;
        if (j == 0) g_gmax = g;
    }
}

extern "C" __global__ void __launch_bounds__(NTH, 1)
spooky_qpass(const float* __restrict__ Q, const float* __restrict__ V,
             float* __restrict__ out, int ntot, int nbt) {
    extern __shared__ __align__(16) char sm[];
    const uint32_t sb = smem_u32(sm);
    float* s_h  = (float*)(sm + SO_H);
    float* s_S  = (float*)(sm + SO_S);
    float* redM = (float*)(sm + SO_RED);          // [128 rows][4 wc]
    float* redW = (float*)(sm + SO_RED + 2048);
    float* redN = (float*)(sm + SO_RED + 4096);
    float* s_sc = (float*)(sm + SO_SC);
    int*   s_nt = (int*)(sm + SO_CT);
    const int tid = threadIdx.x, wid = tid >> 5, lane = tid & 31;
    const int lq = lane >> 2, lr = lane & 3;
    const int wr = wid & 1, wc = wid >> 1;
    const int rb = wr * 64, cb = wc * 64;

    if (tid == 0) s_nt[0] = atomicAdd(&g_ctrQ, 1);
    __syncthreads();
    int rt = s_nt[0];
    if (rt >= nbt) return;

    s_S[tid] = g_S[tid];
    load_B(sm, tid);
    load_A(Q, rt * TM, sm, s_h, tid);
    __syncthreads();

    const float gmx = g_gmax;

    while (true) {
        const int base = rt * TM;
        float c[4][8][4];
        gemm_warp(sb, rb, cb, lane, c);

        float h8[8];
        #pragma unroll
        for (int s = 0; s < 8; ++s)
            h8[s] = s_h[rb + (s >> 1) * 16 + lq + (s & 1) * 8];

        // round 1: per-row max (warp-local cols, then cross-warp via smem)
        #pragma unroll
        for (int s = 0; s < 8; ++s) {
            int mf = s >> 1, hi = s & 1;
            float m = c[mf][0][hi * 2];
            #pragma unroll
            for (int nf = 0; nf < 8; ++nf) {
                m = fmaxf(m, c[mf][nf][hi * 2]);
                m = fmaxf(m, c[mf][nf][hi * 2 + 1]);
            }
            m = fmaxf(m, __shfl_xor_sync(0xffffffffu, m, 1));
            m = fmaxf(m, __shfl_xor_sync(0xffffffffu, m, 2));
            if (lr == 0) redM[(rb + mf * 16 + lq + hi * 8) * 4 + wc] = m;
        }
        if (tid == 0) s_nt[0] = atomicAdd(&g_ctrQ, 1);

        // kp scratch reload (fragment order, coalesced 128B) — issue early
        uint32_t pk[64];
        {
            const uint4* src = g_UK4 + ((size_t)rt * 8 + wid) * 512 + lane * 16;
            #pragma unroll
            for (int q = 0; q < 16; ++q) {
                uint4 t = src[q];
                pk[4 * q] = t.x; pk[4 * q + 1] = t.y;
                pk[4 * q + 2] = t.z; pk[4 * q + 3] = t.w;
            }
        }
        __syncthreads();

        float hb8[8];
        #pragma unroll
        for (int s = 0; s < 8; ++s) {
            int rloc = rb + (s >> 1) * 16 + lq + (s & 1) * 8;
            float rm = fmaxf(fmaxf(redM[rloc * 4], redM[rloc * 4 + 1]),
                             fmaxf(redM[rloc * 4 + 2], redM[rloc * 4 + 3]));
            hb8[s] = h8[s] + rm;
        }
        const int nrt = s_nt[0];
        const float ebm = __expf(g_bmax[rt] - gmx);
        if (nrt < nbt) load_A(Q, nrt * TM, sm, s_h, tid);   // prefetch overlap

        // round 2: w and norm partials
        #pragma unroll
        for (int s = 0; s < 8; ++s) {
            int mf = s >> 1, hi = s & 1;
            int rloc = rb + mf * 16 + lq + hi * 8;
            float hb = hb8[s];
            float wa = 0.f, na = 0.f;
            #pragma unroll
            for (int nf = 0; nf < 8; ++nf) {
                __half2 hh = *(__half2*)&pk[(mf * 8 + nf) * 2 + hi];
                float2 kf = __half22float2(hh);
                #pragma unroll
                for (int e1 = 0; e1 < 2; ++e1) {
                    int col = cb + nf * 8 + lr * 2 + e1;
                    float qp = __expf(c[mf][nf][hi * 2 + e1] - hb) + 1e-4f;
                    float kp = (e1 ? kf.y : kf.x) * ebm + 1e-4f;
                    wa += qp * kp;
                    na += qp * s_S[col];
                }
            }
            wa += __shfl_xor_sync(0xffffffffu, wa, 1);
            wa += __shfl_xor_sync(0xffffffffu, wa, 2);
            na += __shfl_xor_sync(0xffffffffu, na, 1);
            na += __shfl_xor_sync(0xffffffffu, na, 2);
            if (lr == 0) { redW[rloc * 4 + wc] = wa; redN[rloc * 4 + wc] = na; }
        }
        __syncthreads();

        if (tid < TM) {
            float w = redW[tid * 4] + redW[tid * 4 + 1] + redW[tid * 4 + 2] + redW[tid * 4 + 3];
            float n = redN[tid * 4] + redN[tid * 4 + 1] + redN[tid * 4 + 2] + redN[tid * 4 + 3];
            s_sc[tid] = (w * (1.f / 256.f)) / (n * (1.f / 16.f) + 1e-8f);
        }
        __syncthreads();

        #pragma unroll
        for (int it = 0; it < 16; ++it) {
            int r = wid * 16 + it;
            float scv = s_sc[r];
            size_t o = (size_t)(base + r) * KD + lane * 4;
            float4 v = *(const float4*)(V + o);
            v.x *= scv; v.y *= scv; v.z *= scv; v.w *= scv;
            *(float4*)(out + o) = v;
        }
        __syncthreads();
        if (nrt >= nbt) break;
        rt = nrt;
    }
}

// ---------------- launcher ----------------
extern "C" void kernel_launch(void* const* d_in, const int* in_sizes, int n_in,
                              void* d_out, int out_size) {
    const float* Q     = (const float*)d_in[0];
    const float* K     = (const float*)d_in[1];
    const float* V     = (const float*)d_in[2];
    const float* omega = (const float*)d_in[3];
    const int n  = in_sizes[0] / KD;
    const int nb = n / TM;

    cudaFuncSetAttribute(spooky_kpass, cudaFuncAttributeMaxDynamicSharedMemorySize, SMEM_BYTES);
    cudaFuncSetAttribute(spooky_qpass, cudaFuncAttributeMaxDynamicSharedMemorySize, SMEM_BYTES);

    spooky_prep<<<MD, KD>>>(omega);
    spooky_kpass<<<PGRID, NTH, SMEM_BYTES>>>(K, n, nb);
    spooky_fin<<<MD, 256>>>(nb, n);
    spooky_qpass<<<PGRID, NTH, SMEM_BYTES>>>(Q, V, (float*)d_out, n, nb);
}